// round 15
// baseline (speedup 1.0000x reference)
#include <cuda_runtime.h>
#include <cstdint>
#include <math.h>

#define BDIM 16384
#define HDIM 512
#define KDIM 1024
#define LN_EPS 1e-5f

// ---------------- scratch (__device__ globals; allocation-free rule) -------
__device__ float g_Wr[(size_t)2048 * KDIM];      // 8MB tf32 W reordered
__device__ float g_biasr[2048];                  // bias reordered
__device__ float g_Wp[(size_t)HDIM * HDIM];      // 1MB tf32 Wp
__device__ float g_cell_raw[(size_t)BDIM * HDIM];
__device__ float g_o[(size_t)BDIM * HDIM];
__device__ float g_m[(size_t)BDIM * HDIM];       // tf32-rounded o*tanh(LN(cell))

// n' reorder: n' = (h>>3)*32 + gate*8 + (h&7)
//   -> inverse: gate = (n'>>3)&3 ; h = ((n'>>5)<<3) | (n'&7)

// ---------------- helpers ---------------------------------------------------
__device__ __forceinline__ uint32_t smem_to_u32(const void* p) {
    uint32_t a;
    asm("{ .reg .u64 t; cvta.to.shared.u64 t, %1; cvt.u32.u64 %0, t; }" : "=r"(a) : "l"(p));
    return a;
}
__device__ __forceinline__ float ftf32(float x) {   // round-to-nearest tf32
    asm("cvt.rna.tf32.f32 %0, %0;" : "+f"(x));
    return x;
}
__device__ __forceinline__ float sigmoidf_(float x) { return 1.0f / (1.0f + __expf(-x)); }

__device__ __forceinline__ void cp_async16(uint32_t saddr, const float* gptr) {
    uint64_t g;
    asm("cvta.to.global.u64 %0, %1;" : "=l"(g) : "l"(gptr));
    asm volatile("cp.async.cg.shared.global [%0], [%1], 16;" :: "r"(saddr), "l"(g) : "memory");
}
#define CP_COMMIT() asm volatile("cp.async.commit_group;" ::: "memory")
#define CP_WAIT2()  asm volatile("cp.async.wait_group 2;" ::: "memory")

__device__ __forceinline__ void mma_tf32(float& c0, float& c1, float& c2, float& c3,
                                         uint32_t a0, uint32_t a1, uint32_t a2, uint32_t a3,
                                         uint32_t b0, uint32_t b1) {
    asm volatile(
        "mma.sync.aligned.m16n8k8.row.col.f32.tf32.tf32.f32 "
        "{%0,%1,%2,%3}, {%4,%5,%6,%7}, {%8,%9}, {%0,%1,%2,%3};"
        : "+f"(c0), "+f"(c1), "+f"(c2), "+f"(c3)
        : "r"(a0), "r"(a1), "r"(a2), "r"(a3), "r"(b0), "r"(b1));
}

// ---------------- kernel 0: convert/reorder weights to tf32 ----------------
__global__ __launch_bounds__(256)
void prep_kernel(const float* __restrict__ W, const float* __restrict__ bias,
                 const float* __restrict__ Wp)
{
    const size_t tid = (size_t)blockIdx.x * blockDim.x + threadIdx.x;
    const size_t nth = (size_t)gridDim.x * blockDim.x;

    for (size_t i = tid; i < (size_t)2048 * 256; i += nth) {
        int np = (int)(i >> 8); int kq = (int)(i & 255);
        int gate = (np >> 3) & 3;
        int hh   = ((np >> 5) << 3) | (np & 7);
        float4 v = *reinterpret_cast<const float4*>(W + (size_t)(gate * 512 + hh) * 1024 + kq * 4);
        v.x = ftf32(v.x); v.y = ftf32(v.y); v.z = ftf32(v.z); v.w = ftf32(v.w);
        *reinterpret_cast<float4*>(g_Wr + (size_t)np * 1024 + kq * 4) = v;
    }
    for (size_t i = tid; i < (size_t)512 * 128; i += nth) {
        int n = (int)(i >> 7); int kq = (int)(i & 127);
        float4 v = *reinterpret_cast<const float4*>(Wp + (size_t)n * 512 + kq * 4);
        v.x = ftf32(v.x); v.y = ftf32(v.y); v.z = ftf32(v.z); v.w = ftf32(v.w);
        *reinterpret_cast<float4*>(g_Wp + (size_t)n * 512 + kq * 4) = v;
    }
    for (size_t i = tid; i < 2048; i += nth) {
        int gate = ((int)i >> 3) & 3;
        int hh   = (((int)i >> 5) << 3) | ((int)i & 7);
        g_biasr[i] = bias[gate * 512 + hh];
    }
}

// ---------------- GEMM mainloop: acc[128x256] = A[128,K] x B[256,K]^T ------
// 512 threads = 16 warps (2m x 8n), warp tile 64x32 (4x4 m16n8k8) -> 4
// warps/SMSP for latency hiding. A rows from A0 (k<512) / A1 (k>=512), both
// row-length 512; tf32 rounding in fragment regs when ROUND_A.
// 4-stage cp.async pipeline, one __syncthreads per k-iter.
static constexpr int AS_FLOATS = 128 * 36;           // 4608
static constexpr int BS_FLOATS = 256 * 36;           // 9216
static constexpr int STAGE_FLOATS = AS_FLOATS + BS_FLOATS;
static constexpr int SMEM_DYN = 4 * STAGE_FLOATS * 4;   // 221184 B

template<int KITERS, int LDB, bool ROUND_A>
__device__ __forceinline__ void gemm_mainloop(const float* __restrict__ A0,
                                              const float* __restrict__ A1,
                                              const float* __restrict__ B,
                                              int b0, int n0,
                                              float acc[4][4][4], float* sm)
{
    const int tid  = threadIdx.x;
    const int lane = tid & 31;
    const int wid  = tid >> 5;          // 0..15
    const int wm   = wid >> 3;          // 0..1
    const int wn   = wid & 7;           // 0..7
    const uint32_t sbase = smem_to_u32(sm);

    const int cm = tid >> 3;            // 0..63 (row for copy)
    const int kg = tid & 7;             // 0..7  (16B k-group)

    #pragma unroll
    for (int mt = 0; mt < 4; mt++)
        #pragma unroll
        for (int nt = 0; nt < 4; nt++)
            #pragma unroll
            for (int c = 0; c < 4; c++) acc[mt][nt][c] = 0.0f;

    auto issue = [&](int s) {
        const int k0 = s * 32;
        const float* Asrc = (k0 < 512) ? A0 : A1;
        const int ac = k0 & 511;
        const uint32_t abuf = sbase + (uint32_t)((s & 3) * STAGE_FLOATS) * 4;
        const uint32_t bbuf = abuf + AS_FLOATS * 4;
        #pragma unroll
        for (int i = 0; i < 2; i++) {                 // A: 128 rows x 8 kg
            int m = cm + i * 64;
            cp_async16(abuf + (uint32_t)(m * 36 + kg * 4) * 4,
                       Asrc + (size_t)(b0 + m) * 512 + ac + kg * 4);
        }
        #pragma unroll
        for (int i = 0; i < 4; i++) {                 // B: 256 rows x 8 kg
            int n = cm + i * 64;
            cp_async16(bbuf + (uint32_t)(n * 36 + kg * 4) * 4,
                       B + (size_t)(n0 + n) * LDB + k0 + kg * 4);
        }
        CP_COMMIT();
    };

    issue(0); issue(1); issue(2);

    const int arow = lane >> 2;         // 0..7
    const int acol = lane & 3;          // 0..3

    for (int it = 0; it < KITERS; ++it) {
        CP_WAIT2();
        __syncthreads();
        if (it + 3 < KITERS) issue(it + 3);

        const float* As = sm + (it & 3) * STAGE_FLOATS;
        const float* Bs = As + AS_FLOATS;
        const uint32_t* Au = reinterpret_cast<const uint32_t*>(As);
        const uint32_t* Bu = reinterpret_cast<const uint32_t*>(Bs);

        #pragma unroll
        for (int ks = 0; ks < 4; ks++) {
            const int kb = ks * 8;
            uint32_t a[4][4];
            #pragma unroll
            for (int mt = 0; mt < 4; mt++) {
                int row = wm * 64 + mt * 16 + arow;
                a[mt][0] = Au[row * 36 + kb + acol];
                a[mt][1] = Au[(row + 8) * 36 + kb + acol];
                a[mt][2] = Au[row * 36 + kb + acol + 4];
                a[mt][3] = Au[(row + 8) * 36 + kb + acol + 4];
                if (ROUND_A) {
                    #pragma unroll
                    for (int q = 0; q < 4; q++)
                        a[mt][q] = __float_as_uint(ftf32(__uint_as_float(a[mt][q])));
                }
            }
            uint32_t bf[4][2];
            #pragma unroll
            for (int nt = 0; nt < 4; nt++) {
                int col = wn * 32 + nt * 8 + arow;
                bf[nt][0] = Bu[col * 36 + kb + acol];
                bf[nt][1] = Bu[col * 36 + kb + acol + 4];
            }
            #pragma unroll
            for (int mt = 0; mt < 4; mt++)
                #pragma unroll
                for (int nt = 0; nt < 4; nt++)
                    mma_tf32(acc[mt][nt][0], acc[mt][nt][1], acc[mt][nt][2], acc[mt][nt][3],
                             a[mt][0], a[mt][1], a[mt][2], a[mt][3],
                             bf[nt][0], bf[nt][1]);
        }
    }
}

// ---------------- kernel 1: gates GEMM + fused LSTM-cell epilogue ----------
// Warp n-range = 32 = exactly one n'-block (8 h x 4 gates, gate-major):
// nt IS the gate index; thread's 2 cols = 2 adjacent h values.
__global__ __launch_bounds__(512, 1)
void gates_mma_kernel(const float* __restrict__ x,
                      const float* __restrict__ h_prev,
                      const float* __restrict__ c_prev)
{
    extern __shared__ float sm[];
    const int b0 = blockIdx.y * 128;
    const int n0 = blockIdx.x * 256;

    float acc[4][4][4];
    gemm_mainloop<32, 1024, true>(x, h_prev, g_Wr, b0, n0, acc, sm);

    const int lane = threadIdx.x & 31;
    const int wid  = threadIdx.x >> 5;
    const int wm   = wid >> 3, wn = wid & 7;
    const int hq   = 2 * (lane & 3);
    const int rowb = lane >> 2;

    const int blk   = n0 + wn * 32;      // n'-block base
    const int hbase = blk >> 2;          // 8*(blk/32)
    float bi[4][2];
    #pragma unroll
    for (int gate = 0; gate < 4; gate++) {
        bi[gate][0] = g_biasr[blk + gate * 8 + hq + 0];
        bi[gate][1] = g_biasr[blk + gate * 8 + hq + 1];
    }
    #pragma unroll
    for (int mt = 0; mt < 4; mt++) {
        #pragma unroll
        for (int r = 0; r < 2; r++) {
            const int b = b0 + wm * 64 + mt * 16 + rowb + r * 8;
            const int h = hbase + hq;
            float2 cp = *reinterpret_cast<const float2*>(c_prev + (size_t)b * 512 + h);
            float cpv[2] = {cp.x, cp.y};
            float cr[2], ov[2];
            #pragma unroll
            for (int hs = 0; hs < 2; hs++) {
                const int c = r * 2 + hs;
                float iv = sigmoidf_(acc[mt][0][c] + bi[0][hs]);
                float fv = sigmoidf_(acc[mt][1][c] + bi[1][hs]);
                float gv = tanhf    (acc[mt][2][c] + bi[2][hs]);
                ov[hs]   = sigmoidf_(acc[mt][3][c] + bi[3][hs]);
                cr[hs] = fv * cpv[hs] + iv * gv;
            }
            *reinterpret_cast<float2*>(g_cell_raw + (size_t)b * 512 + h) = make_float2(cr[0], cr[1]);
            *reinterpret_cast<float2*>(g_o        + (size_t)b * 512 + h) = make_float2(ov[0], ov[1]);
        }
    }
}

// ---------------- kernel 2: LayerNorm + m = tf32(o*tanh(cell_ln)) ----------
__global__ __launch_bounds__(256)
void ln_kernel(const float* __restrict__ gamma,
               const float* __restrict__ beta,
               float* __restrict__ cell_out)
{
    __shared__ float red_s[8];
    __shared__ float red_q[8];

    const int b = blockIdx.x;
    const int t = threadIdx.x;
    const size_t base = (size_t)b * HDIM;

    float2 v = *reinterpret_cast<const float2*>(g_cell_raw + base + 2 * t);
    float s  = v.x + v.y;
    float sq = v.x * v.x + v.y * v.y;
    #pragma unroll
    for (int o = 16; o > 0; o >>= 1) {
        s  += __shfl_xor_sync(0xffffffff, s,  o);
        sq += __shfl_xor_sync(0xffffffff, sq, o);
    }
    const int warp = t >> 5, lane = t & 31;
    if (lane == 0) { red_s[warp] = s; red_q[warp] = sq; }
    __syncthreads();
    if (t < 32) {
        float ss = (t < 8) ? red_s[t] : 0.0f;
        float qq = (t < 8) ? red_q[t] : 0.0f;
        #pragma unroll
        for (int o = 4; o > 0; o >>= 1) {
            ss += __shfl_xor_sync(0xffffffff, ss, o);
            qq += __shfl_xor_sync(0xffffffff, qq, o);
        }
        if (t == 0) { red_s[0] = ss; red_q[0] = qq; }
    }
    __syncthreads();

    const float mu   = red_s[0] * (1.0f / HDIM);
    const float var  = red_q[0] * (1.0f / HDIM) - mu * mu;
    const float rstd = rsqrtf(var + LN_EPS);

    float2 gm = *reinterpret_cast<const float2*>(gamma + 2 * t);
    float2 bt = *reinterpret_cast<const float2*>(beta  + 2 * t);
    float c0 = (v.x - mu) * rstd * gm.x + bt.x;
    float c1 = (v.y - mu) * rstd * gm.y + bt.y;

    float2 ovv = *reinterpret_cast<const float2*>(g_o + base + 2 * t);

    *reinterpret_cast<float2*>(cell_out + base + 2 * t) = make_float2(c0, c1);

    float2 mv;
    mv.x = ftf32(ovv.x * tanhf(c0));
    mv.y = ftf32(ovv.y * tanhf(c1));
    *reinterpret_cast<float2*>(g_m + base + 2 * t) = mv;
}

// ---------------- kernel 3: projection GEMM --------------------------------
__global__ __launch_bounds__(512, 1)
void proj_mma_kernel(float* __restrict__ out)
{
    extern __shared__ float sm[];
    const int b0 = blockIdx.y * 128;
    const int n0 = blockIdx.x * 256;

    float acc[4][4][4];
    gemm_mainloop<16, 512, false>(g_m, g_m, g_Wp, b0, n0, acc, sm);

    const int lane = threadIdx.x & 31;
    const int wid  = threadIdx.x >> 5;
    const int wm   = wid >> 3, wn = wid & 7;
    const int hq   = 2 * (lane & 3);
    const int rowb = lane >> 2;

    #pragma unroll
    for (int nt = 0; nt < 4; nt++) {
        const int n = n0 + wn * 32 + nt * 8 + hq;
        #pragma unroll
        for (int mt = 0; mt < 4; mt++) {
            #pragma unroll
            for (int r = 0; r < 2; r++) {
                const int b = b0 + wm * 64 + mt * 16 + rowb + r * 8;
                *reinterpret_cast<float2*>(out + (size_t)b * 512 + n) =
                    make_float2(acc[mt][nt][r * 2], acc[mt][nt][r * 2 + 1]);
            }
        }
    }
}

// ---------------- launch ----------------------------------------------------
extern "C" void kernel_launch(void* const* d_in, const int* in_sizes, int n_in,
                              void* d_out, int out_size)
{
    const float* x      = (const float*)d_in[0];
    const float* h_prev = (const float*)d_in[1];
    const float* c_prev = (const float*)d_in[2];
    const float* W      = (const float*)d_in[3];
    const float* bias   = (const float*)d_in[4];
    const float* gamma  = (const float*)d_in[5];
    const float* beta   = (const float*)d_in[6];
    const float* Wp     = (const float*)d_in[7];

    float* out      = (float*)d_out;
    float* cell_out = out + (size_t)BDIM * HDIM;

    cudaFuncSetAttribute(gates_mma_kernel, cudaFuncAttributeMaxDynamicSharedMemorySize, SMEM_DYN);
    cudaFuncSetAttribute(proj_mma_kernel,  cudaFuncAttributeMaxDynamicSharedMemorySize, SMEM_DYN);

    prep_kernel<<<512, 256>>>(W, bias, Wp);

    dim3 g1(2048 / 256, BDIM / 128);    // (8, 128) = 1024 CTAs
    gates_mma_kernel<<<g1, 512, SMEM_DYN>>>(x, h_prev, c_prev);

    ln_kernel<<<BDIM, 256>>>(gamma, beta, cell_out);

    dim3 g3(HDIM / 256, BDIM / 128);    // (2, 128) = 256 CTAs
    proj_mma_kernel<<<g3, 512, SMEM_DYN>>>(out);
}

// round 16
// speedup vs baseline: 1.0641x; 1.0641x over previous
#include <cuda_runtime.h>
#include <cstdint>
#include <math.h>

#define BDIM 16384
#define HDIM 512
#define KDIM 1024
#define LN_EPS 1e-5f

// ---------------- scratch (__device__ globals; allocation-free rule) -------
__device__ float g_Wr[(size_t)2048 * KDIM];      // 8MB tf32 W reordered
__device__ float g_biasr[2048];                  // bias reordered
__device__ float g_Wp[(size_t)HDIM * HDIM];      // 1MB tf32 Wp
__device__ float g_cell_raw[(size_t)BDIM * HDIM];
__device__ float g_o[(size_t)BDIM * HDIM];
__device__ float g_m[(size_t)BDIM * HDIM];       // tf32-rounded o*tanh(LN(cell))

// n' reorder: n' = (h>>3)*32 + gate*8 + (h&7)
//   -> inverse: gate = (n'>>3)&3 ; h = ((n'>>5)<<3) | (n'&7)

// ---------------- helpers ---------------------------------------------------
__device__ __forceinline__ uint32_t smem_to_u32(const void* p) {
    uint32_t a;
    asm("{ .reg .u64 t; cvta.to.shared.u64 t, %1; cvt.u32.u64 %0, t; }" : "=r"(a) : "l"(p));
    return a;
}
__device__ __forceinline__ float ftf32(float x) {   // round-to-nearest tf32
    asm("cvt.rna.tf32.f32 %0, %0;" : "+f"(x));
    return x;
}
__device__ __forceinline__ float sigmoidf_(float x) { return 1.0f / (1.0f + __expf(-x)); }

__device__ __forceinline__ void cp_async16(uint32_t saddr, const float* gptr) {
    uint64_t g;
    asm("cvta.to.global.u64 %0, %1;" : "=l"(g) : "l"(gptr));
    asm volatile("cp.async.cg.shared.global [%0], [%1], 16;" :: "r"(saddr), "l"(g) : "memory");
}
#define CP_COMMIT() asm volatile("cp.async.commit_group;" ::: "memory")
#define CP_WAIT2()  asm volatile("cp.async.wait_group 2;" ::: "memory")

__device__ __forceinline__ void mma_tf32(float& c0, float& c1, float& c2, float& c3,
                                         uint32_t a0, uint32_t a1, uint32_t a2, uint32_t a3,
                                         uint32_t b0, uint32_t b1) {
    asm volatile(
        "mma.sync.aligned.m16n8k8.row.col.f32.tf32.tf32.f32 "
        "{%0,%1,%2,%3}, {%4,%5,%6,%7}, {%8,%9}, {%0,%1,%2,%3};"
        : "+f"(c0), "+f"(c1), "+f"(c2), "+f"(c3)
        : "r"(a0), "r"(a1), "r"(a2), "r"(a3), "r"(b0), "r"(b1));
}

// ---------------- kernel 0: convert/reorder weights to tf32 ----------------
__global__ __launch_bounds__(256)
void prep_kernel(const float* __restrict__ W, const float* __restrict__ bias,
                 const float* __restrict__ Wp)
{
    const size_t tid = (size_t)blockIdx.x * blockDim.x + threadIdx.x;
    const size_t nth = (size_t)gridDim.x * blockDim.x;

    for (size_t i = tid; i < (size_t)2048 * 256; i += nth) {
        int np = (int)(i >> 8); int kq = (int)(i & 255);
        int gate = (np >> 3) & 3;
        int hh   = ((np >> 5) << 3) | (np & 7);
        float4 v = *reinterpret_cast<const float4*>(W + (size_t)(gate * 512 + hh) * 1024 + kq * 4);
        v.x = ftf32(v.x); v.y = ftf32(v.y); v.z = ftf32(v.z); v.w = ftf32(v.w);
        *reinterpret_cast<float4*>(g_Wr + (size_t)np * 1024 + kq * 4) = v;
    }
    for (size_t i = tid; i < (size_t)512 * 128; i += nth) {
        int n = (int)(i >> 7); int kq = (int)(i & 127);
        float4 v = *reinterpret_cast<const float4*>(Wp + (size_t)n * 512 + kq * 4);
        v.x = ftf32(v.x); v.y = ftf32(v.y); v.z = ftf32(v.z); v.w = ftf32(v.w);
        *reinterpret_cast<float4*>(g_Wp + (size_t)n * 512 + kq * 4) = v;
    }
    for (size_t i = tid; i < 2048; i += nth) {
        int gate = ((int)i >> 3) & 3;
        int hh   = (((int)i >> 5) << 3) | ((int)i & 7);
        g_biasr[i] = bias[gate * 512 + hh];
    }
}

// ---------------- GEMM mainloop: acc[128x256] = A[128,K] x B[256,K]^T ------
// 256 threads = 8 warps (2m x 4n), warp tile 64x64 (4x8 m16n8k8).
// Fragment-level DOUBLE BUFFERING across ks: load ks+1 fragments before the
// 32 mma of ks, so each warp's LDS (smem crossbar) overlaps its own tensor
// stream instead of phase-aligning at the iteration barrier.
// 4-stage cp.async pipeline, one __syncthreads per k-iter.
static constexpr int AS_FLOATS = 128 * 36;           // 4608
static constexpr int BS_FLOATS = 256 * 36;           // 9216
static constexpr int STAGE_FLOATS = AS_FLOATS + BS_FLOATS;
static constexpr int SMEM_DYN = 4 * STAGE_FLOATS * 4;   // 221184 B

template<int KITERS, int LDB, bool ROUND_A>
__device__ __forceinline__ void gemm_mainloop(const float* __restrict__ A0,
                                              const float* __restrict__ A1,
                                              const float* __restrict__ B,
                                              int b0, int n0,
                                              float acc[4][8][4], float* sm)
{
    const int tid  = threadIdx.x;
    const int lane = tid & 31;
    const int wid  = tid >> 5;
    const int wm   = wid >> 2;          // 0..1
    const int wn   = wid & 3;           // 0..3
    const uint32_t sbase = smem_to_u32(sm);

    const int cm = tid >> 3;            // 0..31 (row for copy)
    const int kg = tid & 7;             // 0..7  (16B k-group)

    #pragma unroll
    for (int mt = 0; mt < 4; mt++)
        #pragma unroll
        for (int nt = 0; nt < 8; nt++)
            #pragma unroll
            for (int c = 0; c < 4; c++) acc[mt][nt][c] = 0.0f;

    auto issue = [&](int s) {
        const int k0 = s * 32;
        const float* Asrc = (k0 < 512) ? A0 : A1;
        const int ac = k0 & 511;
        const uint32_t abuf = sbase + (uint32_t)((s & 3) * STAGE_FLOATS) * 4;
        const uint32_t bbuf = abuf + AS_FLOATS * 4;
        #pragma unroll
        for (int i = 0; i < 4; i++) {                 // A: 128 rows x 8 kg
            int m = cm + i * 32;
            cp_async16(abuf + (uint32_t)(m * 36 + kg * 4) * 4,
                       Asrc + (size_t)(b0 + m) * 512 + ac + kg * 4);
        }
        #pragma unroll
        for (int i = 0; i < 8; i++) {                 // B: 256 rows x 8 kg
            int n = cm + i * 32;
            cp_async16(bbuf + (uint32_t)(n * 36 + kg * 4) * 4,
                       B + (size_t)(n0 + n) * LDB + k0 + kg * 4);
        }
        CP_COMMIT();
    };

    issue(0); issue(1); issue(2);

    const int arow = lane >> 2;         // 0..7
    const int acol = lane & 3;          // 0..3

    // double-buffered fragments
    uint32_t a[2][4][4];
    uint32_t bf[2][8][2];

    for (int it = 0; it < KITERS; ++it) {
        CP_WAIT2();
        __syncthreads();
        if (it + 3 < KITERS) issue(it + 3);

        const float* As = sm + (it & 3) * STAGE_FLOATS;
        const float* Bs = As + AS_FLOATS;
        const uint32_t* Au = reinterpret_cast<const uint32_t*>(As);
        const uint32_t* Bu = reinterpret_cast<const uint32_t*>(Bs);

        auto load_frag = [&](int slot, int ks) {
            const int kb = ks * 8;
            #pragma unroll
            for (int mt = 0; mt < 4; mt++) {
                int row = wm * 64 + mt * 16 + arow;
                a[slot][mt][0] = Au[row * 36 + kb + acol];
                a[slot][mt][1] = Au[(row + 8) * 36 + kb + acol];
                a[slot][mt][2] = Au[row * 36 + kb + acol + 4];
                a[slot][mt][3] = Au[(row + 8) * 36 + kb + acol + 4];
                if (ROUND_A) {
                    #pragma unroll
                    for (int q = 0; q < 4; q++)
                        a[slot][mt][q] = __float_as_uint(ftf32(__uint_as_float(a[slot][mt][q])));
                }
            }
            #pragma unroll
            for (int nt = 0; nt < 8; nt++) {
                int col = wn * 64 + nt * 8 + arow;
                bf[slot][nt][0] = Bu[col * 36 + kb + acol];
                bf[slot][nt][1] = Bu[col * 36 + kb + acol + 4];
            }
        };

        load_frag(0, 0);
        #pragma unroll
        for (int ks = 0; ks < 4; ks++) {
            const int cur = ks & 1;
            if (ks < 3) load_frag(cur ^ 1, ks + 1);   // overlap LDS with mma below
            #pragma unroll
            for (int mt = 0; mt < 4; mt++)
                #pragma unroll
                for (int nt = 0; nt < 8; nt++)
                    mma_tf32(acc[mt][nt][0], acc[mt][nt][1], acc[mt][nt][2], acc[mt][nt][3],
                             a[cur][mt][0], a[cur][mt][1], a[cur][mt][2], a[cur][mt][3],
                             bf[cur][nt][0], bf[cur][nt][1]);
        }
    }
}

// ---------------- kernel 1: gates GEMM + fused LSTM-cell epilogue ----------
__global__ __launch_bounds__(256, 1)
void gates_mma_kernel(const float* __restrict__ x,
                      const float* __restrict__ h_prev,
                      const float* __restrict__ c_prev)
{
    extern __shared__ float sm[];
    const int b0 = blockIdx.y * 128;
    const int n0 = blockIdx.x * 256;

    float acc[4][8][4];
    gemm_mainloop<32, 1024, true>(x, h_prev, g_Wr, b0, n0, acc, sm);

    const int lane = threadIdx.x & 31;
    const int wid  = threadIdx.x >> 5;
    const int wm   = wid >> 2, wn = wid & 3;
    const int hq   = 2 * (lane & 3);
    const int rowb = lane >> 2;

    #pragma unroll
    for (int g32 = 0; g32 < 2; g32++) {
        const int blk   = n0 + wn * 64 + g32 * 32;   // n'-block base (mult of 32)
        const int hbase = blk >> 2;                  // 8*(blk/32)
        float bi[4][2];
        #pragma unroll
        for (int gate = 0; gate < 4; gate++) {
            bi[gate][0] = g_biasr[blk + gate * 8 + hq + 0];
            bi[gate][1] = g_biasr[blk + gate * 8 + hq + 1];
        }
        #pragma unroll
        for (int mt = 0; mt < 4; mt++) {
            #pragma unroll
            for (int r = 0; r < 2; r++) {
                const int b = b0 + wm * 64 + mt * 16 + rowb + r * 8;
                const int h = hbase + hq;
                float2 cp = *reinterpret_cast<const float2*>(c_prev + (size_t)b * 512 + h);
                float cpv[2] = {cp.x, cp.y};
                float cr[2], ov[2];
                #pragma unroll
                for (int hs = 0; hs < 2; hs++) {
                    const int c = r * 2 + hs;
                    float iv = sigmoidf_(acc[mt][g32 * 4 + 0][c] + bi[0][hs]);
                    float fv = sigmoidf_(acc[mt][g32 * 4 + 1][c] + bi[1][hs]);
                    float gv = tanhf    (acc[mt][g32 * 4 + 2][c] + bi[2][hs]);
                    ov[hs]   = sigmoidf_(acc[mt][g32 * 4 + 3][c] + bi[3][hs]);
                    cr[hs] = fv * cpv[hs] + iv * gv;
                }
                *reinterpret_cast<float2*>(g_cell_raw + (size_t)b * 512 + h) = make_float2(cr[0], cr[1]);
                *reinterpret_cast<float2*>(g_o        + (size_t)b * 512 + h) = make_float2(ov[0], ov[1]);
            }
        }
    }
}

// ---------------- kernel 2: LayerNorm + m = tf32(o*tanh(cell_ln)) ----------
__global__ __launch_bounds__(256)
void ln_kernel(const float* __restrict__ gamma,
               const float* __restrict__ beta,
               float* __restrict__ cell_out)
{
    __shared__ float red_s[8];
    __shared__ float red_q[8];

    const int b = blockIdx.x;
    const int t = threadIdx.x;
    const size_t base = (size_t)b * HDIM;

    float2 v = *reinterpret_cast<const float2*>(g_cell_raw + base + 2 * t);
    float s  = v.x + v.y;
    float sq = v.x * v.x + v.y * v.y;
    #pragma unroll
    for (int o = 16; o > 0; o >>= 1) {
        s  += __shfl_xor_sync(0xffffffff, s,  o);
        sq += __shfl_xor_sync(0xffffffff, sq, o);
    }
    const int warp = t >> 5, lane = t & 31;
    if (lane == 0) { red_s[warp] = s; red_q[warp] = sq; }
    __syncthreads();
    if (t < 32) {
        float ss = (t < 8) ? red_s[t] : 0.0f;
        float qq = (t < 8) ? red_q[t] : 0.0f;
        #pragma unroll
        for (int o = 4; o > 0; o >>= 1) {
            ss += __shfl_xor_sync(0xffffffff, ss, o);
            qq += __shfl_xor_sync(0xffffffff, qq, o);
        }
        if (t == 0) { red_s[0] = ss; red_q[0] = qq; }
    }
    __syncthreads();

    const float mu   = red_s[0] * (1.0f / HDIM);
    const float var  = red_q[0] * (1.0f / HDIM) - mu * mu;
    const float rstd = rsqrtf(var + LN_EPS);

    float2 gm = *reinterpret_cast<const float2*>(gamma + 2 * t);
    float2 bt = *reinterpret_cast<const float2*>(beta  + 2 * t);
    float c0 = (v.x - mu) * rstd * gm.x + bt.x;
    float c1 = (v.y - mu) * rstd * gm.y + bt.y;

    float2 ovv = *reinterpret_cast<const float2*>(g_o + base + 2 * t);

    *reinterpret_cast<float2*>(cell_out + base + 2 * t) = make_float2(c0, c1);

    float2 mv;
    mv.x = ftf32(ovv.x * tanhf(c0));
    mv.y = ftf32(ovv.y * tanhf(c1));
    *reinterpret_cast<float2*>(g_m + base + 2 * t) = mv;
}

// ---------------- kernel 3: projection GEMM --------------------------------
__global__ __launch_bounds__(256, 1)
void proj_mma_kernel(float* __restrict__ out)
{
    extern __shared__ float sm[];
    const int b0 = blockIdx.y * 128;
    const int n0 = blockIdx.x * 256;

    float acc[4][8][4];
    gemm_mainloop<16, 512, false>(g_m, g_m, g_Wp, b0, n0, acc, sm);

    const int lane = threadIdx.x & 31;
    const int wid  = threadIdx.x >> 5;
    const int wm   = wid >> 2, wn = wid & 3;
    const int hq   = 2 * (lane & 3);
    const int rowb = lane >> 2;

    #pragma unroll
    for (int nt = 0; nt < 8; nt++) {
        const int n = n0 + wn * 64 + nt * 8 + hq;
        #pragma unroll
        for (int mt = 0; mt < 4; mt++) {
            #pragma unroll
            for (int r = 0; r < 2; r++) {
                const int b = b0 + wm * 64 + mt * 16 + rowb + r * 8;
                *reinterpret_cast<float2*>(out + (size_t)b * 512 + n) =
                    make_float2(acc[mt][nt][r * 2], acc[mt][nt][r * 2 + 1]);
            }
        }
    }
}

// ---------------- launch ----------------------------------------------------
extern "C" void kernel_launch(void* const* d_in, const int* in_sizes, int n_in,
                              void* d_out, int out_size)
{
    const float* x      = (const float*)d_in[0];
    const float* h_prev = (const float*)d_in[1];
    const float* c_prev = (const float*)d_in[2];
    const float* W      = (const float*)d_in[3];
    const float* bias   = (const float*)d_in[4];
    const float* gamma  = (const float*)d_in[5];
    const float* beta   = (const float*)d_in[6];
    const float* Wp     = (const float*)d_in[7];

    float* out      = (float*)d_out;
    float* cell_out = out + (size_t)BDIM * HDIM;

    cudaFuncSetAttribute(gates_mma_kernel, cudaFuncAttributeMaxDynamicSharedMemorySize, SMEM_DYN);
    cudaFuncSetAttribute(proj_mma_kernel,  cudaFuncAttributeMaxDynamicSharedMemorySize, SMEM_DYN);

    prep_kernel<<<512, 256>>>(W, bias, Wp);

    dim3 g1(2048 / 256, BDIM / 128);    // (8, 128) = 1024 CTAs
    gates_mma_kernel<<<g1, 256, SMEM_DYN>>>(x, h_prev, c_prev);

    ln_kernel<<<BDIM, 256>>>(gamma, beta, cell_out);

    dim3 g3(HDIM / 256, BDIM / 128);    // (2, 128) = 256 CTAs
    proj_mma_kernel<<<g3, 256, SMEM_DYN>>>(out);
}

// round 17
// speedup vs baseline: 1.7397x; 1.6349x over previous
#include <cuda_runtime.h>
#include <cuda_fp16.h>
#include <cstdint>
#include <math.h>

#define BDIM 16384
#define HDIM 512
#define KDIM 1024
#define LN_EPS 1e-5f

// ---------------- scratch (__device__ globals; allocation-free rule) -------
__device__ __half g_Ah[(size_t)BDIM * KDIM];     // 32MB fp16 [x|h_prev]
__device__ __half g_Wrh[(size_t)2048 * KDIM];    // 4MB  fp16 W reordered
__device__ float  g_biasr[2048];                 // bias reordered (fp32)
__device__ __half g_Wph[(size_t)HDIM * HDIM];    // 0.5MB fp16 Wp
__device__ float  g_cell_raw[(size_t)BDIM * HDIM];
__device__ float  g_o[(size_t)BDIM * HDIM];
__device__ __half g_mh[(size_t)BDIM * HDIM];     // fp16 o*tanh(LN(cell))

// n' reorder: n' = (h>>3)*32 + gate*8 + (h&7)
//   -> inverse: gate = (n'>>3)&3 ; h = ((n'>>5)<<3) | (n'&7)

// ---------------- helpers ---------------------------------------------------
__device__ __forceinline__ uint32_t smem_to_u32(const void* p) {
    uint32_t a;
    asm("{ .reg .u64 t; cvta.to.shared.u64 t, %1; cvt.u32.u64 %0, t; }" : "=r"(a) : "l"(p));
    return a;
}
__device__ __forceinline__ float sigmoidf_(float x) { return 1.0f / (1.0f + __expf(-x)); }

__device__ __forceinline__ void cp_async16(uint32_t saddr, const void* gptr) {
    uint64_t g;
    asm("cvta.to.global.u64 %0, %1;" : "=l"(g) : "l"(gptr));
    asm volatile("cp.async.cg.shared.global [%0], [%1], 16;" :: "r"(saddr), "l"(g) : "memory");
}
#define CP_COMMIT() asm volatile("cp.async.commit_group;" ::: "memory")
#define CP_WAIT2()  asm volatile("cp.async.wait_group 2;" ::: "memory")

// fp16 MMA, fp32 accumulate. C-fragment layout identical to m16n8k8.
__device__ __forceinline__ void mma_f16(float& c0, float& c1, float& c2, float& c3,
                                        uint32_t a0, uint32_t a1, uint32_t a2, uint32_t a3,
                                        uint32_t b0, uint32_t b1) {
    asm volatile(
        "mma.sync.aligned.m16n8k16.row.col.f32.f16.f16.f32 "
        "{%0,%1,%2,%3}, {%4,%5,%6,%7}, {%8,%9}, {%0,%1,%2,%3};"
        : "+f"(c0), "+f"(c1), "+f"(c2), "+f"(c3)
        : "r"(a0), "r"(a1), "r"(a2), "r"(a3), "r"(b0), "r"(b1));
}

// convert 8 consecutive floats -> 8 halves (one uint4)
__device__ __forceinline__ uint4 cvt8_f32_f16(const float* src) {
    float4 v0 = *reinterpret_cast<const float4*>(src);
    float4 v1 = *reinterpret_cast<const float4*>(src + 4);
    __half2 h0 = __floats2half2_rn(v0.x, v0.y);
    __half2 h1 = __floats2half2_rn(v0.z, v0.w);
    __half2 h2 = __floats2half2_rn(v1.x, v1.y);
    __half2 h3 = __floats2half2_rn(v1.z, v1.w);
    uint4 r;
    r.x = *reinterpret_cast<uint32_t*>(&h0);
    r.y = *reinterpret_cast<uint32_t*>(&h1);
    r.z = *reinterpret_cast<uint32_t*>(&h2);
    r.w = *reinterpret_cast<uint32_t*>(&h3);
    return r;
}

// ---------------- kernel 0: convert/reorder to fp16 ------------------------
__global__ __launch_bounds__(256)
void prep_kernel(const float* __restrict__ x, const float* __restrict__ h,
                 const float* __restrict__ W, const float* __restrict__ bias,
                 const float* __restrict__ Wp)
{
    const size_t tid = (size_t)blockIdx.x * blockDim.x + threadIdx.x;
    const size_t nth = (size_t)gridDim.x * blockDim.x;

    // A = fp16([x | h_prev]) : BDIM x 1024, units of 8 floats
    for (size_t i = tid; i < (size_t)BDIM * 128; i += nth) {
        size_t b = i >> 7; int c8 = (int)(i & 127) * 8;
        const float* src = (c8 < 512) ? (x + b * 512 + c8) : (h + b * 512 + c8 - 512);
        *reinterpret_cast<uint4*>(g_Ah + b * 1024 + c8) = cvt8_f32_f16(src);
    }
    // Wr[n'][k] fp16
    for (size_t i = tid; i < (size_t)2048 * 128; i += nth) {
        int np = (int)(i >> 7); int c8 = (int)(i & 127) * 8;
        int gate = (np >> 3) & 3;
        int hh   = ((np >> 5) << 3) | (np & 7);
        *reinterpret_cast<uint4*>(g_Wrh + (size_t)np * 1024 + c8) =
            cvt8_f32_f16(W + (size_t)(gate * 512 + hh) * 1024 + c8);
    }
    // Wp fp16
    for (size_t i = tid; i < (size_t)512 * 64; i += nth) {
        int n = (int)(i >> 6); int c8 = (int)(i & 63) * 8;
        *reinterpret_cast<uint4*>(g_Wph + (size_t)n * 512 + c8) =
            cvt8_f32_f16(Wp + (size_t)n * 512 + c8);
    }
    // bias reorder (fp32)
    for (size_t i = tid; i < 2048; i += nth) {
        int gate = ((int)i >> 3) & 3;
        int hh   = (((int)i >> 5) << 3) | ((int)i & 7);
        g_biasr[i] = bias[gate * 512 + hh];
    }
}

// ---------------- GEMM mainloop: acc[128x256] = A[128,K] x B[256,K]^T ------
// fp16 operands, fp32 accum. 256 threads = 8 warps (2m x 4n), warp tile
// 64x64 = 4x8 m16n8k16. Stage K-depth 64 halves; rows padded to 72 halves
// (pitch 36 words) -> conflict-free cp.async stores and fragment LDS.
// 4-stage cp.async pipeline, one __syncthreads per k-iter.
static constexpr int A_PITCH_H = 72;                       // halves per row
static constexpr int A_BYTES = 128 * A_PITCH_H * 2;        // 18432
static constexpr int B_BYTES = 256 * A_PITCH_H * 2;        // 36864
static constexpr int STAGE_BYTES = A_BYTES + B_BYTES;      // 55296
static constexpr int SMEM_DYN = 4 * STAGE_BYTES;           // 221184

template<int KITERS, int LDA, int LDB>
__device__ __forceinline__ void gemm_mainloop(const __half* __restrict__ A,
                                              const __half* __restrict__ B,
                                              int b0, int n0,
                                              float acc[4][8][4], char* sm)
{
    const int tid  = threadIdx.x;
    const int lane = tid & 31;
    const int wid  = tid >> 5;
    const int wm   = wid >> 2;          // 0..1
    const int wn   = wid & 3;           // 0..3
    const uint32_t sbase = smem_to_u32(sm);

    const int cm = tid >> 3;            // 0..31 (row for copy)
    const int kg = tid & 7;             // 0..7  (16B = 8-half k-group)

    #pragma unroll
    for (int mt = 0; mt < 4; mt++)
        #pragma unroll
        for (int nt = 0; nt < 8; nt++)
            #pragma unroll
            for (int c = 0; c < 4; c++) acc[mt][nt][c] = 0.0f;

    auto issue = [&](int s) {
        const int k0 = s * 64;
        const uint32_t abuf = sbase + (uint32_t)(s & 3) * STAGE_BYTES;
        const uint32_t bbuf = abuf + A_BYTES;
        #pragma unroll
        for (int i = 0; i < 4; i++) {                 // A: 128 rows x 8 kg
            int m = cm + i * 32;
            cp_async16(abuf + (uint32_t)(m * 144 + kg * 16),
                       A + (size_t)(b0 + m) * LDA + k0 + kg * 8);
        }
        #pragma unroll
        for (int i = 0; i < 8; i++) {                 // B: 256 rows x 8 kg
            int n = cm + i * 32;
            cp_async16(bbuf + (uint32_t)(n * 144 + kg * 16),
                       B + (size_t)(n0 + n) * LDB + k0 + kg * 8);
        }
        CP_COMMIT();
    };

    issue(0); issue(1); issue(2);

    const int arow = lane >> 2;         // 0..7 (groupID)
    const int acol = lane & 3;          // 0..3 (threadID-in-group)

    for (int it = 0; it < KITERS; ++it) {
        CP_WAIT2();
        __syncthreads();
        if (it + 3 < KITERS) issue(it + 3);

        const char* As = sm + (it & 3) * STAGE_BYTES;
        const uint32_t* Au = reinterpret_cast<const uint32_t*>(As);
        const uint32_t* Bu = reinterpret_cast<const uint32_t*>(As + A_BYTES);

        #pragma unroll
        for (int ks = 0; ks < 4; ks++) {              // 4 x k16 = 64
            const int kb = ks * 8;                    // word offset (16 halves)
            uint32_t a[4][4];
            #pragma unroll
            for (int mt = 0; mt < 4; mt++) {
                int row = wm * 64 + mt * 16 + arow;
                a[mt][0] = Au[row * 36 + kb + acol];
                a[mt][1] = Au[(row + 8) * 36 + kb + acol];
                a[mt][2] = Au[row * 36 + kb + acol + 4];
                a[mt][3] = Au[(row + 8) * 36 + kb + acol + 4];
            }
            uint32_t bf[8][2];
            #pragma unroll
            for (int nt = 0; nt < 8; nt++) {
                int col = wn * 64 + nt * 8 + arow;
                bf[nt][0] = Bu[col * 36 + kb + acol];
                bf[nt][1] = Bu[col * 36 + kb + acol + 4];
            }
            #pragma unroll
            for (int mt = 0; mt < 4; mt++)
                #pragma unroll
                for (int nt = 0; nt < 8; nt++)
                    mma_f16(acc[mt][nt][0], acc[mt][nt][1], acc[mt][nt][2], acc[mt][nt][3],
                            a[mt][0], a[mt][1], a[mt][2], a[mt][3],
                            bf[nt][0], bf[nt][1]);
        }
    }
}

// ---------------- kernel 1: gates GEMM + fused LSTM-cell epilogue ----------
__global__ __launch_bounds__(256, 1)
void gates_mma_kernel(const float* __restrict__ c_prev)
{
    extern __shared__ char sm[];
    const int b0 = blockIdx.y * 128;
    const int n0 = blockIdx.x * 256;

    float acc[4][8][4];
    gemm_mainloop<16, 1024, 1024>(g_Ah, g_Wrh, b0, n0, acc, sm);

    const int lane = threadIdx.x & 31;
    const int wid  = threadIdx.x >> 5;
    const int wm   = wid >> 2, wn = wid & 3;
    const int hq   = 2 * (lane & 3);
    const int rowb = lane >> 2;

    #pragma unroll
    for (int g32 = 0; g32 < 2; g32++) {
        const int blk   = n0 + wn * 64 + g32 * 32;   // n'-block base (mult of 32)
        const int hbase = blk >> 2;                  // 8*(blk/32)
        float bi[4][2];
        #pragma unroll
        for (int gate = 0; gate < 4; gate++) {
            bi[gate][0] = g_biasr[blk + gate * 8 + hq + 0];
            bi[gate][1] = g_biasr[blk + gate * 8 + hq + 1];
        }
        #pragma unroll
        for (int mt = 0; mt < 4; mt++) {
            #pragma unroll
            for (int r = 0; r < 2; r++) {
                const int b = b0 + wm * 64 + mt * 16 + rowb + r * 8;
                const int h = hbase + hq;
                float2 cp = *reinterpret_cast<const float2*>(c_prev + (size_t)b * 512 + h);
                float cpv[2] = {cp.x, cp.y};
                float cr[2], ov[2];
                #pragma unroll
                for (int hs = 0; hs < 2; hs++) {
                    const int c = r * 2 + hs;
                    float iv = sigmoidf_(acc[mt][g32 * 4 + 0][c] + bi[0][hs]);
                    float fv = sigmoidf_(acc[mt][g32 * 4 + 1][c] + bi[1][hs]);
                    float gv = tanhf    (acc[mt][g32 * 4 + 2][c] + bi[2][hs]);
                    ov[hs]   = sigmoidf_(acc[mt][g32 * 4 + 3][c] + bi[3][hs]);
                    cr[hs] = fv * cpv[hs] + iv * gv;
                }
                *reinterpret_cast<float2*>(g_cell_raw + (size_t)b * 512 + h) = make_float2(cr[0], cr[1]);
                *reinterpret_cast<float2*>(g_o        + (size_t)b * 512 + h) = make_float2(ov[0], ov[1]);
            }
        }
    }
}

// ---------------- kernel 2: LayerNorm + m = fp16(o*tanh(cell_ln)) ----------
__global__ __launch_bounds__(256)
void ln_kernel(const float* __restrict__ gamma,
               const float* __restrict__ beta,
               float* __restrict__ cell_out)
{
    __shared__ float red_s[8];
    __shared__ float red_q[8];

    const int b = blockIdx.x;
    const int t = threadIdx.x;
    const size_t base = (size_t)b * HDIM;

    float2 v = *reinterpret_cast<const float2*>(g_cell_raw + base + 2 * t);
    float s  = v.x + v.y;
    float sq = v.x * v.x + v.y * v.y;
    #pragma unroll
    for (int o = 16; o > 0; o >>= 1) {
        s  += __shfl_xor_sync(0xffffffff, s,  o);
        sq += __shfl_xor_sync(0xffffffff, sq, o);
    }
    const int warp = t >> 5, lane = t & 31;
    if (lane == 0) { red_s[warp] = s; red_q[warp] = sq; }
    __syncthreads();
    if (t < 32) {
        float ss = (t < 8) ? red_s[t] : 0.0f;
        float qq = (t < 8) ? red_q[t] : 0.0f;
        #pragma unroll
        for (int o = 4; o > 0; o >>= 1) {
            ss += __shfl_xor_sync(0xffffffff, ss, o);
            qq += __shfl_xor_sync(0xffffffff, qq, o);
        }
        if (t == 0) { red_s[0] = ss; red_q[0] = qq; }
    }
    __syncthreads();

    const float mu   = red_s[0] * (1.0f / HDIM);
    const float var  = red_q[0] * (1.0f / HDIM) - mu * mu;
    const float rstd = rsqrtf(var + LN_EPS);

    float2 gm = *reinterpret_cast<const float2*>(gamma + 2 * t);
    float2 bt = *reinterpret_cast<const float2*>(beta  + 2 * t);
    float c0 = (v.x - mu) * rstd * gm.x + bt.x;
    float c1 = (v.y - mu) * rstd * gm.y + bt.y;

    float2 ovv = *reinterpret_cast<const float2*>(g_o + base + 2 * t);

    *reinterpret_cast<float2*>(cell_out + base + 2 * t) = make_float2(c0, c1);

    __half2 mh = __floats2half2_rn(ovv.x * tanhf(c0), ovv.y * tanhf(c1));
    *reinterpret_cast<__half2*>(g_mh + base + 2 * t) = mh;
}

// ---------------- kernel 3: projection GEMM --------------------------------
__global__ __launch_bounds__(256, 1)
void proj_mma_kernel(float* __restrict__ out)
{
    extern __shared__ char sm[];
    const int b0 = blockIdx.y * 128;
    const int n0 = blockIdx.x * 256;

    float acc[4][8][4];
    gemm_mainloop<8, 512, 512>(g_mh, g_Wph, b0, n0, acc, sm);

    const int lane = threadIdx.x & 31;
    const int wid  = threadIdx.x >> 5;
    const int wm   = wid >> 2, wn = wid & 3;
    const int hq   = 2 * (lane & 3);
    const int rowb = lane >> 2;

    #pragma unroll
    for (int nt = 0; nt < 8; nt++) {
        const int n = n0 + wn * 64 + nt * 8 + hq;
        #pragma unroll
        for (int mt = 0; mt < 4; mt++) {
            #pragma unroll
            for (int r = 0; r < 2; r++) {
                const int b = b0 + wm * 64 + mt * 16 + rowb + r * 8;
                *reinterpret_cast<float2*>(out + (size_t)b * 512 + n) =
                    make_float2(acc[mt][nt][r * 2], acc[mt][nt][r * 2 + 1]);
            }
        }
    }
}

// ---------------- launch ----------------------------------------------------
extern "C" void kernel_launch(void* const* d_in, const int* in_sizes, int n_in,
                              void* d_out, int out_size)
{
    const float* x      = (const float*)d_in[0];
    const float* h_prev = (const float*)d_in[1];
    const float* c_prev = (const float*)d_in[2];
    const float* W      = (const float*)d_in[3];
    const float* bias   = (const float*)d_in[4];
    const float* gamma  = (const float*)d_in[5];
    const float* beta   = (const float*)d_in[6];
    const float* Wp     = (const float*)d_in[7];

    float* out      = (float*)d_out;
    float* cell_out = out + (size_t)BDIM * HDIM;

    cudaFuncSetAttribute(gates_mma_kernel, cudaFuncAttributeMaxDynamicSharedMemorySize, SMEM_DYN);
    cudaFuncSetAttribute(proj_mma_kernel,  cudaFuncAttributeMaxDynamicSharedMemorySize, SMEM_DYN);

    prep_kernel<<<2048, 256>>>(x, h_prev, W, bias, Wp);

    dim3 g1(2048 / 256, BDIM / 128);    // (8, 128) = 1024 CTAs
    gates_mma_kernel<<<g1, 256, SMEM_DYN>>>(c_prev);

    ln_kernel<<<BDIM, 256>>>(gamma, beta, cell_out);

    dim3 g3(HDIM / 256, BDIM / 128);    // (2, 128) = 256 CTAs
    proj_mma_kernel<<<g3, 256, SMEM_DYN>>>(out);
}